// round 2
// baseline (speedup 1.0000x reference)
#include <cuda_runtime.h>

#define BB 2
#define LL 2048
#define HID 1024
#define NH 16
#define FDIM 16
#define HDIM 64
#define MTOT (BB*LL)   // 4096

// Scratch (static __device__ — no allocation allowed)
__device__ float g_q[MTOT * NH * FDIM];   // (b*l, h*16)   4 MB
__device__ float g_k[MTOT * NH * FDIM];   // 4 MB
__device__ float g_v[MTOT * HID];         // (b*l, h*64)  16 MB
__device__ float g_o[MTOT * HID];         // 16 MB

// ---------------------------------------------------------------------------
// C[m,n] = sum_k A[m,k] * B[n,k]   (A: MxK row-major, B: NxK row-major)
// 128x128 block tile, BK=8, 8x8 per-thread microtile, 256 threads.
// ---------------------------------------------------------------------------
__global__ void __launch_bounds__(256)
sgemm_nt(const float* __restrict__ A, const float* __restrict__ Bm,
         float* __restrict__ C, int M, int N, int K) {
    __shared__ __align__(16) float As[8][128];
    __shared__ __align__(16) float Bs[8][128];

    const int tid = threadIdx.x;
    const int m0 = blockIdx.y * 128;
    const int n0 = blockIdx.x * 128;

    const int lrow = tid >> 1;          // 0..127
    const int lcol = (tid & 1) * 4;     // 0 or 4

    const float* Ag = A + (size_t)(m0 + lrow) * K + lcol;
    const float* Bg = Bm + (size_t)(n0 + lrow) * K + lcol;

    const int ty = tid >> 4;            // 0..15
    const int tx = tid & 15;            // 0..15

    float acc[8][8];
#pragma unroll
    for (int i = 0; i < 8; i++)
#pragma unroll
        for (int j = 0; j < 8; j++) acc[i][j] = 0.f;

    for (int kk = 0; kk < K; kk += 8) {
        float4 av = *(const float4*)(Ag + kk);
        float4 bv = *(const float4*)(Bg + kk);
        __syncthreads();  // previous iter's compute done before overwrite
        As[lcol + 0][lrow] = av.x;
        As[lcol + 1][lrow] = av.y;
        As[lcol + 2][lrow] = av.z;
        As[lcol + 3][lrow] = av.w;
        Bs[lcol + 0][lrow] = bv.x;
        Bs[lcol + 1][lrow] = bv.y;
        Bs[lcol + 2][lrow] = bv.z;
        Bs[lcol + 3][lrow] = bv.w;
        __syncthreads();
#pragma unroll
        for (int k = 0; k < 8; k++) {
            float a[8], b[8];
            float4 a0 = *(const float4*)&As[k][ty * 8];
            float4 a1 = *(const float4*)&As[k][ty * 8 + 4];
            float4 b0 = *(const float4*)&Bs[k][tx * 8];
            float4 b1 = *(const float4*)&Bs[k][tx * 8 + 4];
            a[0]=a0.x; a[1]=a0.y; a[2]=a0.z; a[3]=a0.w;
            a[4]=a1.x; a[5]=a1.y; a[6]=a1.z; a[7]=a1.w;
            b[0]=b0.x; b[1]=b0.y; b[2]=b0.z; b[3]=b0.w;
            b[4]=b1.x; b[5]=b1.y; b[6]=b1.z; b[7]=b1.w;
#pragma unroll
            for (int i = 0; i < 8; i++)
#pragma unroll
                for (int j = 0; j < 8; j++) acc[i][j] += a[i] * b[j];
        }
    }

#pragma unroll
    for (int i = 0; i < 8; i++) {
        float* crow = C + (size_t)(m0 + ty * 8 + i) * N + n0 + tx * 8;
        *(float4*)(crow)     = make_float4(acc[i][0], acc[i][1], acc[i][2], acc[i][3]);
        *(float4*)(crow + 4) = make_float4(acc[i][4], acc[i][5], acc[i][6], acc[i][7]);
    }
}

// ---------------------------------------------------------------------------
// Feature map: per (b,l,h) row of 16 floats: layernorm (no affine) then
// *gamma + beta, then *scale (scale = FD^-0.5 for q, 1 for k).
// ---------------------------------------------------------------------------
__global__ void featmap(float* __restrict__ t, const float* __restrict__ gamma,
                        const float* __restrict__ beta, float scale, int nrows) {
    int i = blockIdx.x * blockDim.x + threadIdx.x;
    if (i >= nrows) return;
    float* p = t + (size_t)i * 16;
    float v[16];
    float4* p4 = (float4*)p;
#pragma unroll
    for (int c = 0; c < 4; c++) {
        float4 f = p4[c];
        v[4 * c + 0] = f.x; v[4 * c + 1] = f.y; v[4 * c + 2] = f.z; v[4 * c + 3] = f.w;
    }
    float mu = 0.f;
#pragma unroll
    for (int d = 0; d < 16; d++) mu += v[d];
    mu *= (1.f / 16.f);
    float var = 0.f;
#pragma unroll
    for (int d = 0; d < 16; d++) { float dd = v[d] - mu; var += dd * dd; }
    var *= (1.f / 16.f);
    float r = rsqrtf(var + 1e-5f);
#pragma unroll
    for (int d = 0; d < 16; d++)
        v[d] = ((v[d] - mu) * r * __ldg(&gamma[d]) + __ldg(&beta[d])) * scale;
#pragma unroll
    for (int c = 0; c < 4; c++)
        p4[c] = make_float4(v[4 * c], v[4 * c + 1], v[4 * c + 2], v[4 * c + 3]);
}

// ---------------------------------------------------------------------------
// Causal quadratic "rebased" attention:
//   s_ij = (q_i . k_j)^2   for j <= i, else 0
//   o_i  = (sum_j s_ij v_j) / (sum_j s_ij + 1e-5)
// grid: (L/128, B*NH); block: 128 threads; 1 query row per thread.
// ---------------------------------------------------------------------------
__global__ void __launch_bounds__(128)
attn(const float* __restrict__ q, const float* __restrict__ k,
     const float* __restrict__ v, float* __restrict__ o) {
    __shared__ __align__(16) float ks[128][FDIM];
    __shared__ __align__(16) float vs[128][HDIM];

    const int bh = blockIdx.y;
    const int b = bh >> 4;      // /16
    const int h = bh & 15;
    const int qt = blockIdx.x;
    const int tid = threadIdx.x;
    const int qi = qt * 128 + tid;      // query position in sequence

    // Load this thread's q row into registers
    float qreg[16];
    {
        const float* qrow = q + (size_t)(b * LL + qi) * (NH * FDIM) + h * FDIM;
#pragma unroll
        for (int c = 0; c < 4; c++) {
            float4 f = ((const float4*)qrow)[c];
            qreg[4 * c + 0] = f.x; qreg[4 * c + 1] = f.y;
            qreg[4 * c + 2] = f.z; qreg[4 * c + 3] = f.w;
        }
    }

    float acc[HDIM];
#pragma unroll
    for (int e = 0; e < HDIM; e++) acc[e] = 0.f;
    float z = 0.f;

    for (int kt = 0; kt <= qt; kt++) {
        __syncthreads();
        {
            const int kj = kt * 128 + tid;
            const float* krow = k + (size_t)(b * LL + kj) * (NH * FDIM) + h * FDIM;
#pragma unroll
            for (int c = 0; c < 4; c++)
                ((float4*)ks[tid])[c] = ((const float4*)krow)[c];
            const float* vrow = v + (size_t)(b * LL + kj) * HID + h * HDIM;
#pragma unroll
            for (int c = 0; c < 16; c++)
                ((float4*)vs[tid])[c] = ((const float4*)vrow)[c];
        }
        __syncthreads();

        const int jmax = (kt == qt) ? tid : 127;
        for (int j = 0; j <= jmax; j++) {
            float s = 0.f;
            const float4* kr = (const float4*)ks[j];
#pragma unroll
            for (int c = 0; c < 4; c++) {
                float4 f = kr[c];
                s += qreg[4 * c + 0] * f.x + qreg[4 * c + 1] * f.y +
                     qreg[4 * c + 2] * f.z + qreg[4 * c + 3] * f.w;
            }
            s = s * s;
            z += s;
            const float4* vr = (const float4*)vs[j];
#pragma unroll
            for (int c = 0; c < 16; c++) {
                float4 f = vr[c];
                acc[4 * c + 0] += s * f.x;
                acc[4 * c + 1] += s * f.y;
                acc[4 * c + 2] += s * f.z;
                acc[4 * c + 3] += s * f.w;
            }
        }
    }

    const float inv = 1.f / (z + 1e-5f);
    float* orow = o + (size_t)(b * LL + qi) * HID + h * HDIM;
#pragma unroll
    for (int c = 0; c < 16; c++)
        ((float4*)orow)[c] = make_float4(acc[4 * c + 0] * inv, acc[4 * c + 1] * inv,
                                         acc[4 * c + 2] * inv, acc[4 * c + 3] * inv);
}

// ---------------------------------------------------------------------------
extern "C" void kernel_launch(void* const* d_in, const int* in_sizes, int n_in,
                              void* d_out, int out_size) {
    const float* x     = (const float*)d_in[0];   // (2,2048,1024)
    const float* Wq    = (const float*)d_in[1];   // (256,1024)
    const float* Wk    = (const float*)d_in[2];   // (256,1024)
    const float* Wv    = (const float*)d_in[3];   // (1024,1024)
    const float* Wo    = (const float*)d_in[4];   // (1024,1024)
    const float* gamma = (const float*)d_in[5];   // (16,)
    const float* beta  = (const float*)d_in[6];   // (16,)
    float* out = (float*)d_out;

    float *q, *k, *v, *o;
    cudaGetSymbolAddress((void**)&q, g_q);
    cudaGetSymbolAddress((void**)&k, g_k);
    cudaGetSymbolAddress((void**)&v, g_v);
    cudaGetSymbolAddress((void**)&o, g_o);

    // Projections
    sgemm_nt<<<dim3(2, 32), 256>>>(x, Wq, q, MTOT, NH * FDIM, HID);
    sgemm_nt<<<dim3(2, 32), 256>>>(x, Wk, k, MTOT, NH * FDIM, HID);
    sgemm_nt<<<dim3(8, 32), 256>>>(x, Wv, v, MTOT, HID, HID);

    // Feature maps (q also gets the FD^-0.5 = 0.25 scale)
    const int nrows = MTOT * NH;
    featmap<<<(nrows + 255) / 256, 256>>>(q, gamma, beta, 0.25f, nrows);
    featmap<<<(nrows + 255) / 256, 256>>>(k, gamma, beta, 1.0f, nrows);

    // Causal quadratic attention
    attn<<<dim3(LL / 128, BB * NH), 128>>>(q, k, v, o);

    // Output projection
    sgemm_nt<<<dim3(8, 32), 256>>>(o, Wo, out, MTOT, HID, HID);
}

// round 4
// speedup vs baseline: 1.3045x; 1.3045x over previous
#include <cuda_runtime.h>

#define BB 2
#define LL 2048
#define HID 1024
#define NH 16
#define FDIM 16
#define HDIM 64
#define MTOT (BB*LL)   // 4096
#define BK 16

// Scratch (static __device__ — no allocation allowed)
__device__ float g_q[MTOT * NH * FDIM];   // (b*l, h*16)   4 MB
__device__ float g_k[MTOT * NH * FDIM];   // 4 MB
__device__ float g_v[MTOT * HID];         // (b*l, h*64)  16 MB
__device__ float g_o[MTOT * HID];         // 16 MB

// ---------------------------------------------------------------------------
// Core tile body: C[m,n] = sum_k A[m,k]*B[n,k], 128x128 tile, BK=16,
// double-buffered smem (one __syncthreads per K-step), register prefetch.
// 256 threads, 8x8 microtile per thread.
// ---------------------------------------------------------------------------
__device__ __forceinline__ void sgemm_tile(const float* __restrict__ A,
                                           const float* __restrict__ Bm,
                                           float* __restrict__ C,
                                           int m0, int n0, int K, int ldc) {
    __shared__ __align__(16) float As[2][BK][128];
    __shared__ __align__(16) float Bs[2][BK][128];

    const int tid  = threadIdx.x;
    const int lrow = tid >> 1;          // 0..127
    const int lcol = (tid & 1) * 8;     // 0 or 8

    const float* Ag = A  + (size_t)(m0 + lrow) * K + lcol;
    const float* Bg = Bm + (size_t)(n0 + lrow) * K + lcol;

    const int ty = tid >> 4;            // 0..15
    const int tx = tid & 15;            // 0..15

    float acc[8][8];
#pragma unroll
    for (int i = 0; i < 8; i++)
#pragma unroll
        for (int j = 0; j < 8; j++) acc[i][j] = 0.f;

    float4 a0, a1, b0, b1;

#define QK_STORE_TILE(bufi)                                                     \
    do {                                                                        \
        As[bufi][lcol + 0][lrow] = a0.x; As[bufi][lcol + 1][lrow] = a0.y;       \
        As[bufi][lcol + 2][lrow] = a0.z; As[bufi][lcol + 3][lrow] = a0.w;       \
        As[bufi][lcol + 4][lrow] = a1.x; As[bufi][lcol + 5][lrow] = a1.y;       \
        As[bufi][lcol + 6][lrow] = a1.z; As[bufi][lcol + 7][lrow] = a1.w;       \
        Bs[bufi][lcol + 0][lrow] = b0.x; Bs[bufi][lcol + 1][lrow] = b0.y;       \
        Bs[bufi][lcol + 2][lrow] = b0.z; Bs[bufi][lcol + 3][lrow] = b0.w;       \
        Bs[bufi][lcol + 4][lrow] = b1.x; Bs[bufi][lcol + 5][lrow] = b1.y;       \
        Bs[bufi][lcol + 6][lrow] = b1.z; Bs[bufi][lcol + 7][lrow] = b1.w;       \
    } while (0)

    // Prologue: tile 0 -> buffer 0
    a0 = *(const float4*)(Ag);     a1 = *(const float4*)(Ag + 4);
    b0 = *(const float4*)(Bg);     b1 = *(const float4*)(Bg + 4);
    QK_STORE_TILE(0);
    __syncthreads();

    int buf = 0;
    for (int kk = BK; kk <= K; kk += BK) {
        const bool more = (kk < K);
        if (more) {  // prefetch next tile into registers (hides gmem latency)
            a0 = *(const float4*)(Ag + kk);  a1 = *(const float4*)(Ag + kk + 4);
            b0 = *(const float4*)(Bg + kk);  b1 = *(const float4*)(Bg + kk + 4);
        }
#pragma unroll
        for (int k = 0; k < BK; k++) {
            float a[8], b[8];
            float4 ra0 = *(const float4*)&As[buf][k][ty * 8];
            float4 ra1 = *(const float4*)&As[buf][k][ty * 8 + 4];
            float4 rb0 = *(const float4*)&Bs[buf][k][tx * 8];
            float4 rb1 = *(const float4*)&Bs[buf][k][tx * 8 + 4];
            a[0]=ra0.x; a[1]=ra0.y; a[2]=ra0.z; a[3]=ra0.w;
            a[4]=ra1.x; a[5]=ra1.y; a[6]=ra1.z; a[7]=ra1.w;
            b[0]=rb0.x; b[1]=rb0.y; b[2]=rb0.z; b[3]=rb0.w;
            b[4]=rb1.x; b[5]=rb1.y; b[6]=rb1.z; b[7]=rb1.w;
#pragma unroll
            for (int i = 0; i < 8; i++)
#pragma unroll
                for (int j = 0; j < 8; j++) acc[i][j] += a[i] * b[j];
        }
        if (more) {
            QK_STORE_TILE(buf ^ 1);   // other buffer: safe, prev iter synced
            __syncthreads();
            buf ^= 1;
        }
    }
#undef QK_STORE_TILE

#pragma unroll
    for (int i = 0; i < 8; i++) {
        float* crow = C + (size_t)(m0 + ty * 8 + i) * ldc + n0 + tx * 8;
        *(float4*)(crow)     = make_float4(acc[i][0], acc[i][1], acc[i][2], acc[i][3]);
        *(float4*)(crow + 4) = make_float4(acc[i][4], acc[i][5], acc[i][6], acc[i][7]);
    }
}

// Generic N x K (both 128-multiples), ldc = N
__global__ void __launch_bounds__(256)
sgemm_nt(const float* __restrict__ A, const float* __restrict__ Bm,
         float* __restrict__ C, int K, int ldc) {
    sgemm_tile(A, Bm, C, blockIdx.y * 128, blockIdx.x * 128, K, ldc);
}

// Fused Q+K projection: one launch, 4 x-blocks (2 for Wq->q, 2 for Wk->k)
__global__ void __launch_bounds__(256)
sgemm_qk(const float* __restrict__ x,
         const float* __restrict__ Wq, const float* __restrict__ Wk,
         float* __restrict__ q, float* __restrict__ k) {
    const int bx = blockIdx.x;   // 0..3
    const float* Bm = (bx < 2) ? Wq : Wk;
    float* C        = (bx < 2) ? q  : k;
    const int n0 = (bx & 1) * 128;
    sgemm_tile(x, Bm, C, blockIdx.y * 128, n0, HID, NH * FDIM);
}

// ---------------------------------------------------------------------------
// Feature map on q and k in one launch. First nrows threads -> q (scale .25),
// next nrows -> k (scale 1).
// ---------------------------------------------------------------------------
__global__ void featmap2(float* __restrict__ q, float* __restrict__ k,
                         const float* __restrict__ gamma,
                         const float* __restrict__ beta, int nrows) {
    int i = blockIdx.x * blockDim.x + threadIdx.x;
    float scale;
    float* t;
    if (i < nrows)          { t = q; scale = 0.25f; }
    else if (i < 2 * nrows) { t = k; scale = 1.0f; i -= nrows; }
    else return;

    float* p = t + (size_t)i * 16;
    float v[16];
    float4* p4 = (float4*)p;
#pragma unroll
    for (int c = 0; c < 4; c++) {
        float4 f = p4[c];
        v[4 * c + 0] = f.x; v[4 * c + 1] = f.y; v[4 * c + 2] = f.z; v[4 * c + 3] = f.w;
    }
    float mu = 0.f;
#pragma unroll
    for (int d = 0; d < 16; d++) mu += v[d];
    mu *= (1.f / 16.f);
    float var = 0.f;
#pragma unroll
    for (int d = 0; d < 16; d++) { float dd = v[d] - mu; var += dd * dd; }
    var *= (1.f / 16.f);
    float r = rsqrtf(var + 1e-5f);
#pragma unroll
    for (int d = 0; d < 16; d++)
        v[d] = ((v[d] - mu) * r * __ldg(&gamma[d]) + __ldg(&beta[d])) * scale;
#pragma unroll
    for (int c = 0; c < 4; c++)
        p4[c] = make_float4(v[4 * c], v[4 * c + 1], v[4 * c + 2], v[4 * c + 3]);
}

// ---------------------------------------------------------------------------
// Causal quadratic "rebased" attention:
//   s_ij = (q_i . k_j)^2   for j <= i, else 0
//   o_i  = (sum_j s_ij v_j) / (sum_j s_ij + 1e-5)
// grid: (L/128, B*NH); block: 128 threads; 1 query row per thread.
// Heavy (high-qt) blocks scheduled first to shrink the causal tail.
// ---------------------------------------------------------------------------
__global__ void __launch_bounds__(128)
attn(const float* __restrict__ q, const float* __restrict__ k,
     const float* __restrict__ v, float* __restrict__ o) {
    __shared__ __align__(16) float ks[128][FDIM];
    __shared__ __align__(16) float vs[128][HDIM];

    const int bh = blockIdx.y;
    const int b = bh >> 4;
    const int h = bh & 15;
    const int qt = gridDim.x - 1 - blockIdx.x;   // heavy blocks launch first
    const int tid = threadIdx.x;
    const int qi = qt * 128 + tid;

    float qreg[16];
    {
        const float* qrow = q + (size_t)(b * LL + qi) * (NH * FDIM) + h * FDIM;
#pragma unroll
        for (int c = 0; c < 4; c++) {
            float4 f = ((const float4*)qrow)[c];
            qreg[4 * c + 0] = f.x; qreg[4 * c + 1] = f.y;
            qreg[4 * c + 2] = f.z; qreg[4 * c + 3] = f.w;
        }
    }

    float acc[HDIM];
#pragma unroll
    for (int e = 0; e < HDIM; e++) acc[e] = 0.f;
    float z = 0.f;

    for (int kt = 0; kt <= qt; kt++) {
        __syncthreads();
        {
            const int kj = kt * 128 + tid;
            const float* krow = k + (size_t)(b * LL + kj) * (NH * FDIM) + h * FDIM;
#pragma unroll
            for (int c = 0; c < 4; c++)
                ((float4*)ks[tid])[c] = ((const float4*)krow)[c];
            const float* vrow = v + (size_t)(b * LL + kj) * HID + h * HDIM;
#pragma unroll
            for (int c = 0; c < 16; c++)
                ((float4*)vs[tid])[c] = ((const float4*)vrow)[c];
        }
        __syncthreads();

        const int jmax = (kt == qt) ? tid : 127;
#pragma unroll 2
        for (int j = 0; j <= jmax; j++) {
            float s = 0.f;
            const float4* kr = (const float4*)ks[j];
#pragma unroll
            for (int c = 0; c < 4; c++) {
                float4 f = kr[c];
                s += qreg[4 * c + 0] * f.x + qreg[4 * c + 1] * f.y +
                     qreg[4 * c + 2] * f.z + qreg[4 * c + 3] * f.w;
            }
            s = s * s;
            z += s;
            const float4* vr = (const float4*)vs[j];
#pragma unroll
            for (int c = 0; c < 16; c++) {
                float4 f = vr[c];
                acc[4 * c + 0] += s * f.x;
                acc[4 * c + 1] += s * f.y;
                acc[4 * c + 2] += s * f.z;
                acc[4 * c + 3] += s * f.w;
            }
        }
    }

    const float inv = 1.f / (z + 1e-5f);
    float* orow = o + (size_t)(b * LL + qi) * HID + h * HDIM;
#pragma unroll
    for (int c = 0; c < 16; c++)
        ((float4*)orow)[c] = make_float4(acc[4 * c + 0] * inv, acc[4 * c + 1] * inv,
                                         acc[4 * c + 2] * inv, acc[4 * c + 3] * inv);
}

// ---------------------------------------------------------------------------
extern "C" void kernel_launch(void* const* d_in, const int* in_sizes, int n_in,
                              void* d_out, int out_size) {
    const float* x     = (const float*)d_in[0];   // (2,2048,1024)
    const float* Wq    = (const float*)d_in[1];   // (256,1024)
    const float* Wk    = (const float*)d_in[2];   // (256,1024)
    const float* Wv    = (const float*)d_in[3];   // (1024,1024)
    const float* Wo    = (const float*)d_in[4];   // (1024,1024)
    const float* gamma = (const float*)d_in[5];   // (16,)
    const float* beta  = (const float*)d_in[6];   // (16,)
    float* out = (float*)d_out;

    float *q, *k, *v, *o;
    cudaGetSymbolAddress((void**)&q, g_q);
    cudaGetSymbolAddress((void**)&k, g_k);
    cudaGetSymbolAddress((void**)&v, g_v);
    cudaGetSymbolAddress((void**)&o, g_o);

    // Fused Q+K projection (one wave), then V projection
    sgemm_qk<<<dim3(4, 32), 256>>>(x, Wq, Wk, q, k);
    sgemm_nt<<<dim3(8, 32), 256>>>(x, Wv, v, HID, HID);

    // Feature maps for q (scale FD^-0.5=0.25) and k in one launch
    const int nrows = MTOT * NH;
    featmap2<<<(2 * nrows + 255) / 256, 256>>>(q, k, gamma, beta, nrows);

    // Causal quadratic attention
    attn<<<dim3(LL / 128, BB * NH), 128>>>(q, k, v, o);

    // Output projection
    sgemm_nt<<<dim3(8, 32), 256>>>(o, Wo, out, HID, HID);
}

// round 5
// speedup vs baseline: 1.3291x; 1.0188x over previous
#include <cuda_runtime.h>

#define BB 2
#define LL 2048
#define HID 1024
#define NH 16
#define FDIM 16
#define HDIM 64
#define MTOT (BB*LL)   // 4096
#define BK 16

// Scratch (static __device__ — no allocation allowed)
__device__ float g_q[MTOT * NH * FDIM];   // (b*l, h*16)   4 MB
__device__ float g_k[MTOT * NH * FDIM];   // 4 MB
__device__ float g_v[MTOT * HID];         // (b*l, h*64)  16 MB
__device__ float g_o[MTOT * HID];         // 16 MB

// ---------------------------------------------------------------------------
// Core tile body: C[m,n] = sum_k A[m,k]*B[n,k], 128x128 tile, BK=16,
// double-buffered smem (one __syncthreads per K-step), register prefetch.
// 256 threads, 8x8 microtile per thread.
// ---------------------------------------------------------------------------
__device__ __forceinline__ void sgemm_tile(const float* __restrict__ A,
                                           const float* __restrict__ Bm,
                                           float* __restrict__ C,
                                           int m0, int n0, int K, int ldc) {
    __shared__ __align__(16) float As[2][BK][128];
    __shared__ __align__(16) float Bs[2][BK][128];

    const int tid  = threadIdx.x;
    const int lrow = tid >> 1;          // 0..127
    const int lcol = (tid & 1) * 8;     // 0 or 8

    const float* Ag = A  + (size_t)(m0 + lrow) * K + lcol;
    const float* Bg = Bm + (size_t)(n0 + lrow) * K + lcol;

    const int ty = tid >> 4;            // 0..15
    const int tx = tid & 15;            // 0..15

    float acc[8][8];
#pragma unroll
    for (int i = 0; i < 8; i++)
#pragma unroll
        for (int j = 0; j < 8; j++) acc[i][j] = 0.f;

    float4 a0, a1, b0, b1;

#define QK_STORE_TILE(bufi)                                                     \
    do {                                                                        \
        As[bufi][lcol + 0][lrow] = a0.x; As[bufi][lcol + 1][lrow] = a0.y;       \
        As[bufi][lcol + 2][lrow] = a0.z; As[bufi][lcol + 3][lrow] = a0.w;       \
        As[bufi][lcol + 4][lrow] = a1.x; As[bufi][lcol + 5][lrow] = a1.y;       \
        As[bufi][lcol + 6][lrow] = a1.z; As[bufi][lcol + 7][lrow] = a1.w;       \
        Bs[bufi][lcol + 0][lrow] = b0.x; Bs[bufi][lcol + 1][lrow] = b0.y;       \
        Bs[bufi][lcol + 2][lrow] = b0.z; Bs[bufi][lcol + 3][lrow] = b0.w;       \
        Bs[bufi][lcol + 4][lrow] = b1.x; Bs[bufi][lcol + 5][lrow] = b1.y;       \
        Bs[bufi][lcol + 6][lrow] = b1.z; Bs[bufi][lcol + 7][lrow] = b1.w;       \
    } while (0)

    // Prologue: tile 0 -> buffer 0
    a0 = *(const float4*)(Ag);     a1 = *(const float4*)(Ag + 4);
    b0 = *(const float4*)(Bg);     b1 = *(const float4*)(Bg + 4);
    QK_STORE_TILE(0);
    __syncthreads();

    int buf = 0;
    for (int kk = BK; kk <= K; kk += BK) {
        const bool more = (kk < K);
        if (more) {  // prefetch next tile into registers (hides gmem latency)
            a0 = *(const float4*)(Ag + kk);  a1 = *(const float4*)(Ag + kk + 4);
            b0 = *(const float4*)(Bg + kk);  b1 = *(const float4*)(Bg + kk + 4);
        }
#pragma unroll
        for (int k = 0; k < BK; k++) {
            float a[8], b[8];
            float4 ra0 = *(const float4*)&As[buf][k][ty * 8];
            float4 ra1 = *(const float4*)&As[buf][k][ty * 8 + 4];
            float4 rb0 = *(const float4*)&Bs[buf][k][tx * 8];
            float4 rb1 = *(const float4*)&Bs[buf][k][tx * 8 + 4];
            a[0]=ra0.x; a[1]=ra0.y; a[2]=ra0.z; a[3]=ra0.w;
            a[4]=ra1.x; a[5]=ra1.y; a[6]=ra1.z; a[7]=ra1.w;
            b[0]=rb0.x; b[1]=rb0.y; b[2]=rb0.z; b[3]=rb0.w;
            b[4]=rb1.x; b[5]=rb1.y; b[6]=rb1.z; b[7]=rb1.w;
#pragma unroll
            for (int i = 0; i < 8; i++)
#pragma unroll
                for (int j = 0; j < 8; j++) acc[i][j] += a[i] * b[j];
        }
        if (more) {
            QK_STORE_TILE(buf ^ 1);   // other buffer: safe, prev iter synced
            __syncthreads();
            buf ^= 1;
        }
    }
#undef QK_STORE_TILE

#pragma unroll
    for (int i = 0; i < 8; i++) {
        float* crow = C + (size_t)(m0 + ty * 8 + i) * ldc + n0 + tx * 8;
        *(float4*)(crow)     = make_float4(acc[i][0], acc[i][1], acc[i][2], acc[i][3]);
        *(float4*)(crow + 4) = make_float4(acc[i][4], acc[i][5], acc[i][6], acc[i][7]);
    }
}

// Generic N x K (both 128-multiples), ldc = N
__global__ void __launch_bounds__(256)
sgemm_nt(const float* __restrict__ A, const float* __restrict__ Bm,
         float* __restrict__ C, int K, int ldc) {
    sgemm_tile(A, Bm, C, blockIdx.y * 128, blockIdx.x * 128, K, ldc);
}

// Fused Q+K projection: one launch, 4 x-blocks (2 for Wq->q, 2 for Wk->k)
__global__ void __launch_bounds__(256)
sgemm_qk(const float* __restrict__ x,
         const float* __restrict__ Wq, const float* __restrict__ Wk,
         float* __restrict__ q, float* __restrict__ k) {
    const int bx = blockIdx.x;   // 0..3
    const float* Bm = (bx < 2) ? Wq : Wk;
    float* C        = (bx < 2) ? q  : k;
    const int n0 = (bx & 1) * 128;
    sgemm_tile(x, Bm, C, blockIdx.y * 128, n0, HID, NH * FDIM);
}

// ---------------------------------------------------------------------------
// Feature map on q and k in one launch. First nrows threads -> q (scale .25),
// next nrows -> k (scale 1).
// ---------------------------------------------------------------------------
__global__ void featmap2(float* __restrict__ q, float* __restrict__ k,
                         const float* __restrict__ gamma,
                         const float* __restrict__ beta, int nrows) {
    int i = blockIdx.x * blockDim.x + threadIdx.x;
    float scale;
    float* t;
    if (i < nrows)          { t = q; scale = 0.25f; }
    else if (i < 2 * nrows) { t = k; scale = 1.0f; i -= nrows; }
    else return;

    float* p = t + (size_t)i * 16;
    float v[16];
    float4* p4 = (float4*)p;
#pragma unroll
    for (int c = 0; c < 4; c++) {
        float4 f = p4[c];
        v[4 * c + 0] = f.x; v[4 * c + 1] = f.y; v[4 * c + 2] = f.z; v[4 * c + 3] = f.w;
    }
    float mu = 0.f;
#pragma unroll
    for (int d = 0; d < 16; d++) mu += v[d];
    mu *= (1.f / 16.f);
    float var = 0.f;
#pragma unroll
    for (int d = 0; d < 16; d++) { float dd = v[d] - mu; var += dd * dd; }
    var *= (1.f / 16.f);
    float r = rsqrtf(var + 1e-5f);
#pragma unroll
    for (int d = 0; d < 16; d++)
        v[d] = ((v[d] - mu) * r * __ldg(&gamma[d]) + __ldg(&beta[d])) * scale;
#pragma unroll
    for (int c = 0; c < 4; c++)
        p4[c] = make_float4(v[4 * c], v[4 * c + 1], v[4 * c + 2], v[4 * c + 3]);
}

// ---------------------------------------------------------------------------
// Causal quadratic "rebased" attention:
//   s_ij = (q_i . k_j)^2   for j <= i, else 0
//   o_i  = (sum_j s_ij v_j) / (sum_j s_ij + 1e-5)
// grid: (L/128, B*NH); block: 128 threads; 1 query row per thread.
// Heavy (high-qt) blocks scheduled first to shrink the causal tail.
// ---------------------------------------------------------------------------
__global__ void __launch_bounds__(128)
attn(const float* __restrict__ q, const float* __restrict__ k,
     const float* __restrict__ v, float* __restrict__ o) {
    __shared__ __align__(16) float ks[128][FDIM];
    __shared__ __align__(16) float vs[128][HDIM];

    const int bh = blockIdx.y;
    const int b = bh >> 4;
    const int h = bh & 15;
    const int qt = gridDim.x - 1 - blockIdx.x;   // heavy blocks launch first
    const int tid = threadIdx.x;
    const int qi = qt * 128 + tid;

    float qreg[16];
    {
        const float* qrow = q + (size_t)(b * LL + qi) * (NH * FDIM) + h * FDIM;
#pragma unroll
        for (int c = 0; c < 4; c++) {
            float4 f = ((const float4*)qrow)[c];
            qreg[4 * c + 0] = f.x; qreg[4 * c + 1] = f.y;
            qreg[4 * c + 2] = f.z; qreg[4 * c + 3] = f.w;
        }
    }

    float acc[HDIM];
#pragma unroll
    for (int e = 0; e < HDIM; e++) acc[e] = 0.f;
    float z = 0.f;

    for (int kt = 0; kt <= qt; kt++) {
        __syncthreads();
        {
            const int kj = kt * 128 + tid;
            const float* krow = k + (size_t)(b * LL + kj) * (NH * FDIM) + h * FDIM;
#pragma unroll
            for (int c = 0; c < 4; c++)
                ((float4*)ks[tid])[c] = ((const float4*)krow)[c];
            const float* vrow = v + (size_t)(b * LL + kj) * HID + h * HDIM;
#pragma unroll
            for (int c = 0; c < 16; c++)
                ((float4*)vs[tid])[c] = ((const float4*)vrow)[c];
        }
        __syncthreads();

        const int jmax = (kt == qt) ? tid : 127;
#pragma unroll 2
        for (int j = 0; j <= jmax; j++) {
            float s = 0.f;
            const float4* kr = (const float4*)ks[j];
#pragma unroll
            for (int c = 0; c < 4; c++) {
                float4 f = kr[c];
                s += qreg[4 * c + 0] * f.x + qreg[4 * c + 1] * f.y +
                     qreg[4 * c + 2] * f.z + qreg[4 * c + 3] * f.w;
            }
            s = s * s;
            z += s;
            const float4* vr = (const float4*)vs[j];
#pragma unroll
            for (int c = 0; c < 16; c++) {
                float4 f = vr[c];
                acc[4 * c + 0] += s * f.x;
                acc[4 * c + 1] += s * f.y;
                acc[4 * c + 2] += s * f.z;
                acc[4 * c + 3] += s * f.w;
            }
        }
    }

    const float inv = 1.f / (z + 1e-5f);
    float* orow = o + (size_t)(b * LL + qi) * HID + h * HDIM;
#pragma unroll
    for (int c = 0; c < 16; c++)
        ((float4*)orow)[c] = make_float4(acc[4 * c + 0] * inv, acc[4 * c + 1] * inv,
                                         acc[4 * c + 2] * inv, acc[4 * c + 3] * inv);
}

// ---------------------------------------------------------------------------
extern "C" void kernel_launch(void* const* d_in, const int* in_sizes, int n_in,
                              void* d_out, int out_size) {
    const float* x     = (const float*)d_in[0];   // (2,2048,1024)
    const float* Wq    = (const float*)d_in[1];   // (256,1024)
    const float* Wk    = (const float*)d_in[2];   // (256,1024)
    const float* Wv    = (const float*)d_in[3];   // (1024,1024)
    const float* Wo    = (const float*)d_in[4];   // (1024,1024)
    const float* gamma = (const float*)d_in[5];   // (16,)
    const float* beta  = (const float*)d_in[6];   // (16,)
    float* out = (float*)d_out;

    float *q, *k, *v, *o;
    cudaGetSymbolAddress((void**)&q, g_q);
    cudaGetSymbolAddress((void**)&k, g_k);
    cudaGetSymbolAddress((void**)&v, g_v);
    cudaGetSymbolAddress((void**)&o, g_o);

    // Fused Q+K projection (one wave), then V projection
    sgemm_qk<<<dim3(4, 32), 256>>>(x, Wq, Wk, q, k);
    sgemm_nt<<<dim3(8, 32), 256>>>(x, Wv, v, HID, HID);

    // Feature maps for q (scale FD^-0.5=0.25) and k in one launch
    const int nrows = MTOT * NH;
    featmap2<<<(2 * nrows + 255) / 256, 256>>>(q, k, gamma, beta, nrows);

    // Causal quadratic attention
    attn<<<dim3(LL / 128, BB * NH), 128>>>(q, k, v, o);

    // Output projection
    sgemm_nt<<<dim3(8, 32), 256>>>(o, Wo, out, HID, HID);
}